// round 2
// baseline (speedup 1.0000x reference)
#include <cuda_runtime.h>

#define BDIM 1024
#define TDIM 4096
#define WSZ 10
#define HID 32
#define NPOS (TDIM - WSZ)          /* 4086 */
#define THREADS 256
#define PPT 4
#define POS_PER_CTA (THREADS * PPT) /* 1024 */

__global__ __launch_bounds__(THREADS)
void hurst_mlp_kernel(const float* __restrict__ returns,
                      const float* __restrict__ W1, const float* __restrict__ b1,
                      const float* __restrict__ W2, const float* __restrict__ b2,
                      const float* __restrict__ W3, const float* __restrict__ b3,
                      float* __restrict__ out)
{
    __shared__ float sW1[WSZ * HID];     // [w][j] row-major, rows 128B-aligned
    __shared__ float sW2[HID * HID];     // [k][j] row-major
    __shared__ float sW3[HID];
    __shared__ float sb1[HID];
    __shared__ float sb2[HID];
    __shared__ float sxs[POS_PER_CTA + WSZ + 6]; // input segment + pad

    const int tid = threadIdx.x;
    const int row = blockIdx.y;
    const int p0  = blockIdx.x * POS_PER_CTA;

    // Stage weights (tiny; L2-hot across CTAs)
    for (int i = tid; i < WSZ * HID; i += THREADS) sW1[i] = W1[i];
    for (int i = tid; i < HID * HID; i += THREADS) sW2[i] = W2[i];
    if (tid < HID) { sW3[tid] = W3[tid]; sb1[tid] = b1[tid]; sb2[tid] = b2[tid]; }

    // Stage this CTA's input segment: returns[row][p0 .. p0+POS_PER_CTA+WSZ-1]
    const float* xrow = returns + (long)row * TDIM;
    for (int i = tid; i < POS_PER_CTA + WSZ; i += THREADS) {
        int t = p0 + i;
        sxs[i] = (t < TDIM) ? xrow[t] : 0.0f;
    }
    const float bb3 = b3[0];
    __syncthreads();

    #pragma unroll
    for (int r = 0; r < PPT; r++) {
        const int pl = tid + r * THREADS;   // local position in CTA
        const int p  = p0 + pl;             // global position

        // ---- layer 1: h1 = relu-pending (x @ W1 + b1), x in smem, W1 broadcast LDS.128
        float h1[HID];
        #pragma unroll
        for (int j = 0; j < HID; j++) h1[j] = sb1[j];
        #pragma unroll
        for (int w = 0; w < WSZ; w++) {
            const float xv = sxs[pl + w];
            const float4* wrow = (const float4*)(sW1 + w * HID);
            #pragma unroll
            for (int j4 = 0; j4 < HID / 4; j4++) {
                const float4 wv = wrow[j4];
                h1[4*j4+0] += xv * wv.x;
                h1[4*j4+1] += xv * wv.y;
                h1[4*j4+2] += xv * wv.z;
                h1[4*j4+3] += xv * wv.w;
            }
        }

        // ---- layer 2: h2 = relu(h1) @ W2 + b2
        float h2[HID];
        #pragma unroll
        for (int j = 0; j < HID; j++) h2[j] = sb2[j];
        #pragma unroll
        for (int k = 0; k < HID; k++) {
            const float v = fmaxf(h1[k], 0.0f);
            const float4* wrow = (const float4*)(sW2 + k * HID);
            #pragma unroll
            for (int j4 = 0; j4 < HID / 4; j4++) {
                const float4 wv = wrow[j4];
                h2[4*j4+0] += v * wv.x;
                h2[4*j4+1] += v * wv.y;
                h2[4*j4+2] += v * wv.z;
                h2[4*j4+3] += v * wv.w;
            }
        }

        // ---- layer 3: z = relu(h2) @ W3 + b3 ; out = 0.5*sigmoid(z)
        float z = bb3;
        const float4* w3v = (const float4*)sW3;
        #pragma unroll
        for (int j4 = 0; j4 < HID / 4; j4++) {
            const float4 wv = w3v[j4];
            z += fmaxf(h2[4*j4+0], 0.0f) * wv.x;
            z += fmaxf(h2[4*j4+1], 0.0f) * wv.y;
            z += fmaxf(h2[4*j4+2], 0.0f) * wv.z;
            z += fmaxf(h2[4*j4+3], 0.0f) * wv.w;
        }
        const float o = 0.5f / (1.0f + __expf(-z));

        if (p < NPOS) {
            out[(long)row * TDIM + WSZ + p] = o;
            if (p == 0) {
                #pragma unroll
                for (int c = 0; c < WSZ; c++)
                    out[(long)row * TDIM + c] = o;
            }
        }
    }
}

extern "C" void kernel_launch(void* const* d_in, const int* in_sizes, int n_in,
                              void* d_out, int out_size)
{
    const float* returns = (const float*)d_in[0];
    const float* W1      = (const float*)d_in[1];
    const float* b1      = (const float*)d_in[2];
    const float* W2      = (const float*)d_in[3];
    const float* b2      = (const float*)d_in[4];
    const float* W3      = (const float*)d_in[5];
    const float* b3      = (const float*)d_in[6];
    float* out           = (float*)d_out;

    dim3 grid((NPOS + POS_PER_CTA - 1) / POS_PER_CTA, BDIM); // (4, 1024)
    hurst_mlp_kernel<<<grid, THREADS>>>(returns, W1, b1, W2, b2, W3, b3, out);
}